// round 16
// baseline (speedup 1.0000x reference)
#include <cuda_runtime.h>
#include <cuda_bf16.h>
#include <math.h>
#include <stdint.h>

// Problem constants (fixed shapes per reference)
#define T_MAX 2048
#define HID   2048
#define NQ    32
#define NKV   8
#define HD    64
#define QKV_COLS ((NQ + 2*NKV) * HD)   // 3072
#define K_OFF (NQ * HD)                // 2048
#define V_OFF ((NQ + NKV) * HD)        // 2560

// Scratch (no allocation allowed)
__device__ float g_qkv[T_MAX * QKV_COLS];

__device__ __nv_bfloat16 g_hid_hi[T_MAX * HID];
__device__ __nv_bfloat16 g_hid_lo[T_MAX * HID];
__device__ __nv_bfloat16 g_wqkv_hi[HID * QKV_COLS];
__device__ __nv_bfloat16 g_wqkv_lo[HID * QKV_COLS];
__device__ __nv_bfloat16 g_attn_hi[T_MAX * NQ * HD];
__device__ __nv_bfloat16 g_attn_lo[T_MAX * NQ * HD];
__device__ __nv_bfloat16 g_wout_hi[NQ * HD * HID];
__device__ __nv_bfloat16 g_wout_lo[NQ * HD * HID];

__device__ __nv_bfloat16 g_q_hi[T_MAX * NQ * HD];
__device__ __nv_bfloat16 g_q_lo[T_MAX * NQ * HD];
__device__ __nv_bfloat16 g_k_hi[T_MAX * NKV * HD];
__device__ __nv_bfloat16 g_k_lo[T_MAX * NKV * HD];
__device__ __nv_bfloat16 g_v_hi[T_MAX * NKV * HD];
__device__ __nv_bfloat16 g_v_lo[T_MAX * NKV * HD];

// ---------------------------------------------------------------------------
// PTX helpers
// ---------------------------------------------------------------------------
__device__ __forceinline__ void cp16(uint32_t dst, const void* src) {
    asm volatile("cp.async.cg.shared.global [%0], [%1], 16;" :: "r"(dst), "l"(src));
}
__device__ __forceinline__ void cp_commit() {
    asm volatile("cp.async.commit_group;");
}
__device__ __forceinline__ void cp_wait1() {
    asm volatile("cp.async.wait_group 1;");
}
__device__ __forceinline__ void cp_wait2() {
    asm volatile("cp.async.wait_group 2;");
}
__device__ __forceinline__ void ldm_x4(uint32_t* r, uint32_t a) {
    asm volatile("ldmatrix.sync.aligned.m8n8.x4.shared.b16 {%0,%1,%2,%3}, [%4];"
        : "=r"(r[0]), "=r"(r[1]), "=r"(r[2]), "=r"(r[3]) : "r"(a));
}
__device__ __forceinline__ void ldm_x4_t(uint32_t* r, uint32_t a) {
    asm volatile("ldmatrix.sync.aligned.m8n8.x4.trans.shared.b16 {%0,%1,%2,%3}, [%4];"
        : "=r"(r[0]), "=r"(r[1]), "=r"(r[2]), "=r"(r[3]) : "r"(a));
}
__device__ __forceinline__ void mma16816(float* c, const uint32_t* a, const uint32_t* b) {
    asm volatile(
        "mma.sync.aligned.m16n8k16.row.col.f32.bf16.bf16.f32 "
        "{%0,%1,%2,%3}, {%4,%5,%6,%7}, {%8,%9}, {%0,%1,%2,%3};"
        : "+f"(c[0]), "+f"(c[1]), "+f"(c[2]), "+f"(c[3])
        : "r"(a[0]), "r"(a[1]), "r"(a[2]), "r"(a[3]), "r"(b[0]), "r"(b[1]));
}
__device__ __forceinline__ uint32_t smem_u32(const void* p) {
    return (uint32_t)__cvta_generic_to_shared(p);
}
__device__ __forceinline__ uint32_t pack_bf2(__nv_bfloat16 lo, __nv_bfloat16 hi) {
    __nv_bfloat162 v = __halves2bfloat162(lo, hi);
    return *(uint32_t*)&v;
}

// ---------------------------------------------------------------------------
// Split fp32 -> (hi, lo) bf16 pair
// ---------------------------------------------------------------------------
__global__ __launch_bounds__(256) void split_kernel(
    const float* __restrict__ x, __nv_bfloat16* __restrict__ hi,
    __nv_bfloat16* __restrict__ lo, int n)
{
    int i = (blockIdx.x * 256 + threadIdx.x) * 4;
    if (i >= n) { return; }
    float4 v = *(const float4*)(x + i);
    __nv_bfloat16 h0 = __float2bfloat16_rn(v.x);
    __nv_bfloat16 h1 = __float2bfloat16_rn(v.y);
    __nv_bfloat16 h2 = __float2bfloat16_rn(v.z);
    __nv_bfloat16 h3 = __float2bfloat16_rn(v.w);
    __nv_bfloat16 l0 = __float2bfloat16_rn(v.x - __bfloat162float(h0));
    __nv_bfloat16 l1 = __float2bfloat16_rn(v.y - __bfloat162float(h1));
    __nv_bfloat16 l2 = __float2bfloat16_rn(v.z - __bfloat162float(h2));
    __nv_bfloat16 l3 = __float2bfloat16_rn(v.w - __bfloat162float(h3));
    *(__nv_bfloat162*)(hi + i)     = __halves2bfloat162(h0, h1);
    *(__nv_bfloat162*)(hi + i + 2) = __halves2bfloat162(h2, h3);
    *(__nv_bfloat162*)(lo + i)     = __halves2bfloat162(l0, l1);
    *(__nv_bfloat162*)(lo + i + 2) = __halves2bfloat162(l2, l3);
}

// ---------------------------------------------------------------------------
// bf16x3 GEMM (R10/R12 config): tile 128x128, GBK=16, 4-stage ring,
// 128 threads (4 warps, 2m x 2n, warp tile 64x64), 2 CTAs/SM.
// Split-K via gridDim.z (uneven allowed). Epilogue atomicAdd when split.
// ---------------------------------------------------------------------------
#define GBM 128
#define GBN 128
#define GBK 16
#define SA  24                       // A row stride: 48B (R5-verified)
#define SB  136                      // B row stride: 272B (R5-verified)
#define A_STAGE (2 * GBM * SA)       // 6144 elems
#define B_STAGE (2 * GBK * SB)       // 4352 elems
#define G_SMEM_BYTES ((4 * A_STAGE + 4 * B_STAGE) * 2)   // 83968

__device__ __forceinline__ void g_fill_stage(
    uint32_t as_base, uint32_t bs_base,
    const __nv_bfloat16* __restrict__ Ahi, const __nv_bfloat16* __restrict__ Alo,
    const __nv_bfloat16* __restrict__ Bhi, const __nv_bfloat16* __restrict__ Blo,
    int bm, int bn, int k0, int K, int N, int tid)
{
    #pragma unroll
    for (int i = 0; i < 2; i++) {
        int idx = i * 128 + tid;
        int a_row = idx >> 1;
        int a_c   = (idx & 1) * 8;
        size_t aoff = (size_t)(bm + a_row) * K + k0 + a_c;
        uint32_t so = (uint32_t)((a_row * SA + a_c) * 2);
        cp16(as_base + so, Ahi + aoff);
        cp16(as_base + GBM * SA * 2 + so, Alo + aoff);

        int b_row = idx >> 4;
        int b_col = (idx & 15) * 8;
        size_t boff = (size_t)(k0 + b_row) * N + bn + b_col;
        uint32_t sbo = (uint32_t)((b_row * SB + b_col) * 2);
        cp16(bs_base + sbo, Bhi + boff);
        cp16(bs_base + GBK * SB * 2 + sbo, Blo + boff);
    }
}

__global__ __launch_bounds__(128, 2) void gemm_bf16x3(
    const __nv_bfloat16* __restrict__ Ahi, const __nv_bfloat16* __restrict__ Alo,
    const __nv_bfloat16* __restrict__ Bhi, const __nv_bfloat16* __restrict__ Blo,
    float* __restrict__ C, int M, int N, int K)
{
    extern __shared__ __nv_bfloat16 sm[];
    __nv_bfloat16* As = sm;                 // [4 stages][hi|lo][128*SA]
    __nv_bfloat16* Bs = sm + 4 * A_STAGE;   // [4 stages][hi|lo][16*SB]

    const int tid  = threadIdx.x;
    const int lane = tid & 31;
    const int warp = tid >> 5;
    const int wm   = warp >> 1;    // 0..1
    const int wn   = warp & 1;     // 0..1
    const int bm   = blockIdx.y * GBM;
    const int bn   = blockIdx.x * GBN;

    // uneven split-K: totIters split as base + (z < rem)
    const int totIters = K / GBK;
    const int zc  = gridDim.z;
    const int z   = blockIdx.z;
    const int bIt = totIters / zc;
    const int rem = totIters % zc;
    const int niter = bIt + ((z < rem) ? 1 : 0);
    const int kBase = (z * bIt + ((z < rem) ? z : rem)) * GBK;

    float acc[4][8][4];
    #pragma unroll
    for (int mi = 0; mi < 4; mi++) {
        #pragma unroll
        for (int ni = 0; ni < 8; ni++) {
            acc[mi][ni][0] = 0.0f;
            acc[mi][ni][1] = 0.0f;
            acc[mi][ni][2] = 0.0f;
            acc[mi][ni][3] = 0.0f;
        }
    }

    const uint32_t as0 = smem_u32(As);
    const uint32_t bs0 = smem_u32(Bs);

    // prologue: stages 0,1,2
    #pragma unroll
    for (int p = 0; p < 3; p++) {
        if (p < niter) {
            g_fill_stage(as0 + p * A_STAGE * 2, bs0 + p * B_STAGE * 2,
                         Ahi, Alo, Bhi, Blo, bm, bn, kBase + p * GBK, K, N, tid);
        }
        cp_commit();
    }

    for (int it = 0; it < niter; ++it) {
        cp_wait2();
        __syncthreads();

        if (it + 3 < niter) {
            int s = (it + 3) & 3;
            g_fill_stage(as0 + s * A_STAGE * 2, bs0 + s * B_STAGE * 2,
                         Ahi, Alo, Bhi, Blo, bm, bn, kBase + (it + 3) * GBK, K, N, tid);
        }
        cp_commit();

        const int s = it & 3;
        __nv_bfloat16* asb = As + s * A_STAGE;
        __nv_bfloat16* bsb = Bs + s * B_STAGE;

        uint32_t ah[4][4];
        uint32_t al[4][4];

        #pragma unroll
        for (int mi = 0; mi < 4; mi++) {
            int r = wm * 64 + mi * 16 + (lane & 15);
            int c = (lane >> 4) * 8;
            ldm_x4(ah[mi], smem_u32(asb + r * SA + c));
            ldm_x4(al[mi], smem_u32(asb + GBM * SA + r * SA + c));
        }

        #pragma unroll
        for (int bi = 0; bi < 4; bi++) {
            int r = lane & 15;
            int c = wn * 64 + bi * 16 + (lane >> 4) * 8;
            uint32_t t0[4];
            uint32_t t1[4];
            ldm_x4_t(t0, smem_u32(bsb + r * SB + c));
            ldm_x4_t(t1, smem_u32(bsb + GBK * SB + r * SB + c));
            uint32_t bh0[2]; bh0[0] = t0[0]; bh0[1] = t0[1];
            uint32_t bh1[2]; bh1[0] = t0[2]; bh1[1] = t0[3];
            uint32_t bl0[2]; bl0[0] = t1[0]; bl0[1] = t1[1];
            uint32_t bl1[2]; bl1[0] = t1[2]; bl1[1] = t1[3];

            #pragma unroll
            for (int mi = 0; mi < 4; mi++) {
                mma16816(acc[mi][2 * bi],     ah[mi], bh0);
                mma16816(acc[mi][2 * bi + 1], ah[mi], bh1);
            }
            #pragma unroll
            for (int mi = 0; mi < 4; mi++) {
                mma16816(acc[mi][2 * bi],     ah[mi], bl0);
                mma16816(acc[mi][2 * bi + 1], ah[mi], bl1);
            }
            #pragma unroll
            for (int mi = 0; mi < 4; mi++) {
                mma16816(acc[mi][2 * bi],     al[mi], bh0);
                mma16816(acc[mi][2 * bi + 1], al[mi], bh1);
            }
        }
    }

    const bool split = (gridDim.z > 1);
    #pragma unroll
    for (int mi = 0; mi < 4; mi++) {
        #pragma unroll
        for (int ni = 0; ni < 8; ni++) {
            int r = bm + wm * 64 + mi * 16 + (lane >> 2);
            int c = bn + wn * 64 + ni * 8 + (lane & 3) * 2;
            float* p0 = &C[(size_t)r * N + c];
            float* p1 = &C[(size_t)(r + 8) * N + c];
            if (split) {
                atomicAdd(p0,     acc[mi][ni][0]);
                atomicAdd(p0 + 1, acc[mi][ni][1]);
                atomicAdd(p1,     acc[mi][ni][2]);
                atomicAdd(p1 + 1, acc[mi][ni][3]);
            } else {
                float2 v0;
                float2 v1;
                v0.x = acc[mi][ni][0];
                v0.y = acc[mi][ni][1];
                v1.x = acc[mi][ni][2];
                v1.y = acc[mi][ni][3];
                *(float2*)p0 = v0;
                *(float2*)p1 = v1;
            }
        }
    }
}

// ---------------------------------------------------------------------------
// RMSNorm + RoPE + split, one warp per (token, head). Lane owns (d, d+32).
// ---------------------------------------------------------------------------
__global__ __launch_bounds__(256) void norm_rope_split_kernel(
    const float* __restrict__ qkv, const int* __restrict__ positions,
    const float* __restrict__ q_ln_w, const float* __restrict__ k_ln_w,
    __nv_bfloat16* __restrict__ qhi, __nv_bfloat16* __restrict__ qlo,
    __nv_bfloat16* __restrict__ khi, __nv_bfloat16* __restrict__ klo,
    __nv_bfloat16* __restrict__ vhi, __nv_bfloat16* __restrict__ vlo)
{
    const int gw   = blockIdx.x * 8 + (threadIdx.x >> 5);
    const int lane = threadIdx.x & 31;
    const int head = gw % (NQ + 2 * NKV);
    const int t    = gw / (NQ + 2 * NKV);

    if (head >= NQ + NKV) {
        int vh = head - NQ - NKV;
        const float* base = qkv + (size_t)t * QKV_COLS + V_OFF + vh * HD;
        float x1 = base[lane];
        float x2 = base[lane + 32];
        __nv_bfloat16 h1 = __float2bfloat16_rn(x1);
        __nv_bfloat16 h2 = __float2bfloat16_rn(x2);
        size_t o = (size_t)t * (NKV * HD) + vh * HD + lane;
        vhi[o]      = h1;
        vhi[o + 32] = h2;
        vlo[o]      = __float2bfloat16_rn(x1 - __bfloat162float(h1));
        vlo[o + 32] = __float2bfloat16_rn(x2 - __bfloat162float(h2));
        return;
    }

    const bool isq = (head < NQ);
    const float* base = qkv + (size_t)t * QKV_COLS +
                        (isq ? head * HD : K_OFF + (head - NQ) * HD);
    const float* w = isq ? q_ln_w : k_ln_w;

    float x1 = base[lane];
    float x2 = base[lane + 32];
    float ss = x1 * x1 + x2 * x2;
    #pragma unroll
    for (int o = 16; o > 0; o >>= 1) {
        ss += __shfl_xor_sync(0xffffffff, ss, o);
    }
    float rs = rsqrtf(ss * (1.0f / 64.0f) + 1e-5f);
    float y1 = x1 * rs * w[lane];
    float y2 = x2 * rs * w[lane + 32];

    float pos = (float)positions[t];
    // inv = 1e6^(-lane/32) = exp2f(-lane * log2(1e6)/32), log2(1e6)/32 = 0.62286152
    float inv = exp2f((float)lane * (-0.62286152f));
    float s, c;
    sincosf(pos * inv, &s, &c);
    float o1 = y1 * c - y2 * s;
    float o2 = y2 * c + y1 * s;
    if (isq) {
        o1 *= 0.125f;
        o2 *= 0.125f;
    }

    __nv_bfloat16 h1 = __float2bfloat16_rn(o1);
    __nv_bfloat16 h2 = __float2bfloat16_rn(o2);
    __nv_bfloat16 l1 = __float2bfloat16_rn(o1 - __bfloat162float(h1));
    __nv_bfloat16 l2 = __float2bfloat16_rn(o2 - __bfloat162float(h2));
    if (isq) {
        size_t o = (size_t)t * (NQ * HD) + head * HD + lane;
        qhi[o]      = h1;
        qhi[o + 32] = h2;
        qlo[o]      = l1;
        qlo[o + 32] = l2;
    } else {
        size_t o = (size_t)t * (NKV * HD) + (head - NQ) * HD + lane;
        khi[o]      = h1;
        khi[o + 32] = h2;
        klo[o]      = l1;
        klo[o + 32] = l2;
    }
}

// ---------------------------------------------------------------------------
// Tensor-core causal flash attention (bf16x3, mma.sync).
// PAIRED q-tiles: block (pq, h) handles q-tiles (NT-1-pq) then (pq).
// Every block does exactly NT+2 tile-iters -> one uniform wave (256 blocks).
// ---------------------------------------------------------------------------
#define AST 72
#define AREG (4 * 64 * AST)
#define A_SMEM_BYTES (3 * AREG * 2)

__global__ __launch_bounds__(256, 2) void attn_mma_kernel(
    const __nv_bfloat16* __restrict__ qhi, const __nv_bfloat16* __restrict__ qlo,
    const __nv_bfloat16* __restrict__ khi, const __nv_bfloat16* __restrict__ klo,
    const __nv_bfloat16* __restrict__ vhi, const __nv_bfloat16* __restrict__ vlo,
    __nv_bfloat16* __restrict__ ohi, __nv_bfloat16* __restrict__ olo)
{
    extern __shared__ __nv_bfloat16 sm[];

    const int tid  = threadIdx.x;
    const int lane = tid & 31;
    const int warp = tid >> 5;
    const int h    = blockIdx.y;
    const int kvh  = h >> 2;

    for (int pass = 0; pass < 2; pass++) {
        const int qtile = (pass == 0) ? (2 * gridDim.x - 1 - blockIdx.x)
                                      : blockIdx.x;
        const int qbase = qtile * 128;
        const int ntiles = 2 * qtile + 2;

        // ---- prologue: Q into region0 + KV tile0 into region1 (group0) ----
        #pragma unroll
        for (int i = 0; i < 4; i++) {
            int lin = i * 256 + tid;
            int row = lin >> 3;
            int c = (lin & 7) * 8;
            size_t g = (size_t)(qbase + row) * (NQ * HD) + h * HD + c;
            cp16(smem_u32(sm + row * AST + c), qhi + g);
            cp16(smem_u32(sm + 128 * AST + row * AST + c), qlo + g);
        }
        {
            __nv_bfloat16* rb = sm + AREG;
            #pragma unroll
            for (int i = 0; i < 2; i++) {
                int lin = i * 256 + tid;
                int row = lin >> 3;
                int c = (lin & 7) * 8;
                size_t g = (size_t)row * (NKV * HD) + kvh * HD + c;
                cp16(smem_u32(rb + row * AST + c), khi + g);
                cp16(smem_u32(rb + 64 * AST + row * AST + c), klo + g);
                cp16(smem_u32(rb + 128 * AST + row * AST + c), vhi + g);
                cp16(smem_u32(rb + 192 * AST + row * AST + c), vlo + g);
            }
        }
        cp_commit();
        if (ntiles > 1) {
            __nv_bfloat16* rb = sm + 2 * AREG;
            #pragma unroll
            for (int i = 0; i < 2; i++) {
                int lin = i * 256 + tid;
                int row = lin >> 3;
                int c = (lin & 7) * 8;
                size_t g = (size_t)(64 + row) * (NKV * HD) + kvh * HD + c;
                cp16(smem_u32(rb + row * AST + c), khi + g);
                cp16(smem_u32(rb + 64 * AST + row * AST + c), klo + g);
                cp16(smem_u32(rb + 128 * AST + row * AST + c), vhi + g);
                cp16(smem_u32(rb + 192 * AST + row * AST + c), vlo + g);
            }
        }
        cp_commit();

        cp_wait1();
        __syncthreads();

        uint32_t aqh[4][4];
        uint32_t aql[4][4];
        #pragma unroll
        for (int ks = 0; ks < 4; ks++) {
            int r = warp * 16 + (lane & 15);
            int c = ks * 16 + (lane >> 4) * 8;
            ldm_x4(aqh[ks], smem_u32(sm + r * AST + c));
            ldm_x4(aql[ks], smem_u32(sm + 128 * AST + r * AST + c));
        }
        __syncthreads();

        float oacc[8][4];
        #pragma unroll
        for (int ni = 0; ni < 8; ni++) {
            oacc[ni][0] = 0.0f; oacc[ni][1] = 0.0f;
            oacc[ni][2] = 0.0f; oacc[ni][3] = 0.0f;
        }
        float m0 = -1e30f, m1 = -1e30f, l0 = 0.0f, l1 = 0.0f;

        const int rowlim = qbase + warp * 16 + 15;

        for (int it = 0; it < ntiles; it++) {
            cp_wait1();
            __syncthreads();

            if (it + 2 < ntiles) {
                __nv_bfloat16* rb = sm + ((it + 3) % 3) * AREG;
                int k0n = (it + 2) * 64;
                #pragma unroll
                for (int i = 0; i < 2; i++) {
                    int lin = i * 256 + tid;
                    int row = lin >> 3;
                    int c = (lin & 7) * 8;
                    size_t g = (size_t)(k0n + row) * (NKV * HD) + kvh * HD + c;
                    cp16(smem_u32(rb + row * AST + c), khi + g);
                    cp16(smem_u32(rb + 64 * AST + row * AST + c), klo + g);
                    cp16(smem_u32(rb + 128 * AST + row * AST + c), vhi + g);
                    cp16(smem_u32(rb + 192 * AST + row * AST + c), vlo + g);
                }
            }
            cp_commit();

            const int k0 = it * 64;
            if (k0 > rowlim) { continue; }

            __nv_bfloat16* rb = sm + ((it + 1) % 3) * AREG;
            __nv_bfloat16* kbh = rb;
            __nv_bfloat16* kbl = rb + 64 * AST;
            __nv_bfloat16* vbh = rb + 128 * AST;
            __nv_bfloat16* vbl = rb + 192 * AST;

            float sacc[8][4];
            #pragma unroll
            for (int ni = 0; ni < 8; ni++) {
                sacc[ni][0] = 0.0f; sacc[ni][1] = 0.0f;
                sacc[ni][2] = 0.0f; sacc[ni][3] = 0.0f;
            }

            const int krow = ((lane >> 4) << 3) + (lane & 7);
            #pragma unroll
            for (int ks = 0; ks < 4; ks++) {
                int kcol = ks * 16 + ((lane >> 3) & 1) * 8;
                #pragma unroll
                for (int kg = 0; kg < 4; kg++) {
                    uint32_t th[4];
                    uint32_t tl[4];
                    ldm_x4(th, smem_u32(kbh + (kg * 16 + krow) * AST + kcol));
                    ldm_x4(tl, smem_u32(kbl + (kg * 16 + krow) * AST + kcol));
                    uint32_t b0h[2]; b0h[0] = th[0]; b0h[1] = th[1];
                    uint32_t b1h[2]; b1h[0] = th[2]; b1h[1] = th[3];
                    uint32_t b0l[2]; b0l[0] = tl[0]; b0l[1] = tl[1];
                    uint32_t b1l[2]; b1l[0] = tl[2]; b1l[1] = tl[3];
                    mma16816(sacc[2 * kg],     aqh[ks], b0h);
                    mma16816(sacc[2 * kg + 1], aqh[ks], b1h);
                    mma16816(sacc[2 * kg],     aqh[ks], b0l);
                    mma16816(sacc[2 * kg + 1], aqh[ks], b1l);
                    mma16816(sacc[2 * kg],     aql[ks], b0h);
                    mma16816(sacc[2 * kg + 1], aql[ks], b1h);
                }
            }

            if (k0 + 64 > qbase + warp * 16) {
                int row0 = qbase + warp * 16 + (lane >> 2);
                #pragma unroll
                for (int ni = 0; ni < 8; ni++) {
                    int colk = k0 + ni * 8 + (lane & 3) * 2;
                    if (colk     > row0)     { sacc[ni][0] = -1e30f; }
                    if (colk + 1 > row0)     { sacc[ni][1] = -1e30f; }
                    if (colk     > row0 + 8) { sacc[ni][2] = -1e30f; }
                    if (colk + 1 > row0 + 8) { sacc[ni][3] = -1e30f; }
                }
            }

            float nm0 = m0;
            float nm1 = m1;
            #pragma unroll
            for (int ni = 0; ni < 8; ni++) {
                nm0 = fmaxf(nm0, fmaxf(sacc[ni][0], sacc[ni][1]));
                nm1 = fmaxf(nm1, fmaxf(sacc[ni][2], sacc[ni][3]));
            }
            nm0 = fmaxf(nm0, __shfl_xor_sync(0xffffffff, nm0, 1));
            nm0 = fmaxf(nm0, __shfl_xor_sync(0xffffffff, nm0, 2));
            nm1 = fmaxf(nm1, __shfl_xor_sync(0xffffffff, nm1, 1));
            nm1 = fmaxf(nm1, __shfl_xor_sync(0xffffffff, nm1, 2));

            float sc0 = __expf(m0 - nm0);
            float sc1 = __expf(m1 - nm1);
            m0 = nm0;
            m1 = nm1;
            l0 *= sc0;
            l1 *= sc1;

            uint32_t phi[8][2];
            uint32_t plo[8][2];
            #pragma unroll
            for (int ni = 0; ni < 8; ni++) {
                float p0 = __expf(sacc[ni][0] - nm0);
                float p1 = __expf(sacc[ni][1] - nm0);
                float p2 = __expf(sacc[ni][2] - nm1);
                float p3 = __expf(sacc[ni][3] - nm1);
                l0 += p0 + p1;
                l1 += p2 + p3;
                __nv_bfloat16 h0 = __float2bfloat16_rn(p0);
                __nv_bfloat16 h1 = __float2bfloat16_rn(p1);
                __nv_bfloat16 h2 = __float2bfloat16_rn(p2);
                __nv_bfloat16 h3 = __float2bfloat16_rn(p3);
                phi[ni][0] = pack_bf2(h0, h1);
                phi[ni][1] = pack_bf2(h2, h3);
                plo[ni][0] = pack_bf2(__float2bfloat16_rn(p0 - __bfloat162float(h0)),
                                      __float2bfloat16_rn(p1 - __bfloat162float(h1)));
                plo[ni][1] = pack_bf2(__float2bfloat16_rn(p2 - __bfloat162float(h2)),
                                      __float2bfloat16_rn(p3 - __bfloat162float(h3)));
                oacc[ni][0] *= sc0;
                oacc[ni][1] *= sc0;
                oacc[ni][2] *= sc1;
                oacc[ni][3] *= sc1;
            }

            #pragma unroll
            for (int ks = 0; ks < 4; ks++) {
                uint32_t aph[4];
                uint32_t apl[4];
                aph[0] = phi[2 * ks][0];     aph[1] = phi[2 * ks][1];
                aph[2] = phi[2 * ks + 1][0]; aph[3] = phi[2 * ks + 1][1];
                apl[0] = plo[2 * ks][0];     apl[1] = plo[2 * ks][1];
                apl[2] = plo[2 * ks + 1][0]; apl[3] = plo[2 * ks + 1][1];
                int vrow = ks * 16 + (lane & 15);
                #pragma unroll
                for (int nd = 0; nd < 4; nd++) {
                    int vcol = nd * 16 + (lane >> 4) * 8;
                    uint32_t th[4];
                    uint32_t tl[4];
                    ldm_x4_t(th, smem_u32(vbh + vrow * AST + vcol));
                    ldm_x4_t(tl, smem_u32(vbl + vrow * AST + vcol));
                    uint32_t b0h[2]; b0h[0] = th[0]; b0h[1] = th[1];
                    uint32_t b1h[2]; b1h[0] = th[2]; b1h[1] = th[3];
                    uint32_t b0l[2]; b0l[0] = tl[0]; b0l[1] = tl[1];
                    uint32_t b1l[2]; b1l[0] = tl[2]; b1l[1] = tl[3];
                    mma16816(oacc[2 * nd],     aph, b0h);
                    mma16816(oacc[2 * nd + 1], aph, b1h);
                    mma16816(oacc[2 * nd],     aph, b0l);
                    mma16816(oacc[2 * nd + 1], aph, b1l);
                    mma16816(oacc[2 * nd],     apl, b0h);
                    mma16816(oacc[2 * nd + 1], apl, b1h);
                }
            }
        }

        l0 += __shfl_xor_sync(0xffffffff, l0, 1);
        l0 += __shfl_xor_sync(0xffffffff, l0, 2);
        l1 += __shfl_xor_sync(0xffffffff, l1, 1);
        l1 += __shfl_xor_sync(0xffffffff, l1, 2);
        float inv0 = 1.0f / l0;
        float inv1 = 1.0f / l1;

        int row0 = qbase + warp * 16 + (lane >> 2);
        #pragma unroll
        for (int ni = 0; ni < 8; ni++) {
            int col = h * HD + ni * 8 + (lane & 3) * 2;
            float f0 = oacc[ni][0] * inv0;
            float f1 = oacc[ni][1] * inv0;
            float f2 = oacc[ni][2] * inv1;
            float f3 = oacc[ni][3] * inv1;
            __nv_bfloat16 h0 = __float2bfloat16_rn(f0);
            __nv_bfloat16 h1 = __float2bfloat16_rn(f1);
            __nv_bfloat16 h2 = __float2bfloat16_rn(f2);
            __nv_bfloat16 h3 = __float2bfloat16_rn(f3);
            __nv_bfloat162 hv0 = __halves2bfloat162(h0, h1);
            __nv_bfloat162 hv1 = __halves2bfloat162(h2, h3);
            __nv_bfloat162 lv0 = __halves2bfloat162(
                __float2bfloat16_rn(f0 - __bfloat162float(h0)),
                __float2bfloat16_rn(f1 - __bfloat162float(h1)));
            __nv_bfloat162 lv1 = __halves2bfloat162(
                __float2bfloat16_rn(f2 - __bfloat162float(h2)),
                __float2bfloat16_rn(f3 - __bfloat162float(h3)));
            *(__nv_bfloat162*)&ohi[(size_t)row0 * (NQ * HD) + col] = hv0;
            *(__nv_bfloat162*)&olo[(size_t)row0 * (NQ * HD) + col] = lv0;
            *(__nv_bfloat162*)&ohi[(size_t)(row0 + 8) * (NQ * HD) + col] = hv1;
            *(__nv_bfloat162*)&olo[(size_t)(row0 + 8) * (NQ * HD) + col] = lv1;
        }

        __syncthreads();   // drain before next pass reuses smem regions
    }
}

// ---------------------------------------------------------------------------
// Launch
// ---------------------------------------------------------------------------
extern "C" void kernel_launch(void* const* d_in, const int* in_sizes, int n_in,
                              void* d_out, int out_size)
{
    const int*   positions = (const int*)d_in[0];
    const float* hidden    = (const float*)d_in[1];
    const float* w_qkv     = (const float*)d_in[2];
    const float* w_out     = (const float*)d_in[3];
    const float* q_ln_w    = (const float*)d_in[4];
    const float* k_ln_w    = (const float*)d_in[5];
    float* out = (float*)d_out;

    const int T = in_sizes[1] / HID;   // 2048

    float* qkv;
    __nv_bfloat16 *hid_hi, *hid_lo, *wqkv_hi, *wqkv_lo;
    __nv_bfloat16 *attn_hi, *attn_lo, *wout_hi, *wout_lo;
    __nv_bfloat16 *q_hi, *q_lo, *k_hi, *k_lo, *v_hi, *v_lo;
    cudaGetSymbolAddress((void**)&qkv, g_qkv);
    cudaGetSymbolAddress((void**)&hid_hi, g_hid_hi);
    cudaGetSymbolAddress((void**)&hid_lo, g_hid_lo);
    cudaGetSymbolAddress((void**)&wqkv_hi, g_wqkv_hi);
    cudaGetSymbolAddress((void**)&wqkv_lo, g_wqkv_lo);
    cudaGetSymbolAddress((void**)&attn_hi, g_attn_hi);
    cudaGetSymbolAddress((void**)&attn_lo, g_attn_lo);
    cudaGetSymbolAddress((void**)&wout_hi, g_wout_hi);
    cudaGetSymbolAddress((void**)&wout_lo, g_wout_lo);
    cudaGetSymbolAddress((void**)&q_hi, g_q_hi);
    cudaGetSymbolAddress((void**)&q_lo, g_q_lo);
    cudaGetSymbolAddress((void**)&k_hi, g_k_hi);
    cudaGetSymbolAddress((void**)&k_lo, g_k_lo);
    cudaGetSymbolAddress((void**)&v_hi, g_v_hi);
    cudaGetSymbolAddress((void**)&v_lo, g_v_lo);

    // Splits for GEMM inputs + zero split-K accumulators
    {
        cudaMemsetAsync(qkv, 0, (size_t)T * QKV_COLS * sizeof(float), 0);
        cudaMemsetAsync(out, 0, (size_t)T * HID * sizeof(float), 0);
        int n1 = T * HID;
        split_kernel<<<n1 / 1024, 256>>>(hidden, hid_hi, hid_lo, n1);
        int n2 = HID * QKV_COLS;
        split_kernel<<<n2 / 1024, 256>>>(w_qkv, wqkv_hi, wqkv_lo, n2);
        int n3 = NQ * HD * HID;
        split_kernel<<<n3 / 1024, 256>>>(w_out, wout_hi, wout_lo, n3);
    }

    cudaFuncSetAttribute(gemm_bf16x3,
                         cudaFuncAttributeMaxDynamicSharedMemorySize, G_SMEM_BYTES);

    // 1) QKV projection (uneven split-K=3: work-stealing packs 1152 slices)
    {
        dim3 grid(QKV_COLS / GBN, T / GBM, 3);
        gemm_bf16x3<<<grid, 128, G_SMEM_BYTES>>>(hid_hi, hid_lo, wqkv_hi, wqkv_lo,
                                                 qkv, T, QKV_COLS, HID);
    }

    // 2) RMSNorm + RoPE + split (q scaled by 1/8)
    {
        int nwarps = T * (NQ + 2 * NKV);
        norm_rope_split_kernel<<<nwarps / 8, 256>>>(qkv, positions, q_ln_w, k_ln_w,
                                                    q_hi, q_lo, k_hi, k_lo, v_hi, v_lo);
    }

    // 3) Paired-tile causal attention: 8 pairs x 32 heads = 256 uniform blocks
    {
        cudaFuncSetAttribute(attn_mma_kernel,
                             cudaFuncAttributeMaxDynamicSharedMemorySize, A_SMEM_BYTES);
        dim3 grid(T / 128 / 2, NQ);
        attn_mma_kernel<<<grid, 256, A_SMEM_BYTES>>>(q_hi, q_lo, k_hi, k_lo,
                                                     v_hi, v_lo, attn_hi, attn_lo);
    }

    // 4) Output projection (split-K=3: 768 slices, work-stealing packs them)
    {
        dim3 grid(HID / GBN, T / GBM, 3);
        gemm_bf16x3<<<grid, 128, G_SMEM_BYTES>>>(attn_hi, attn_lo, wout_hi, wout_lo,
                                                 out, T, HID, NQ * HD);
    }
}

// round 17
// speedup vs baseline: 1.0326x; 1.0326x over previous
#include <cuda_runtime.h>
#include <cuda_bf16.h>
#include <math.h>
#include <stdint.h>

// Problem constants (fixed shapes per reference)
#define T_MAX 2048
#define HID   2048
#define NQ    32
#define NKV   8
#define HD    64
#define QKV_COLS ((NQ + 2*NKV) * HD)   // 3072
#define K_OFF (NQ * HD)                // 2048
#define V_OFF ((NQ + NKV) * HD)        // 2560

// Scratch (no allocation allowed)
__device__ float g_qkv[T_MAX * QKV_COLS];

__device__ __nv_bfloat16 g_hid_hi[T_MAX * HID];
__device__ __nv_bfloat16 g_hid_lo[T_MAX * HID];
__device__ __nv_bfloat16 g_wqkv_hi[HID * QKV_COLS];
__device__ __nv_bfloat16 g_wqkv_lo[HID * QKV_COLS];
__device__ __nv_bfloat16 g_attn_hi[T_MAX * NQ * HD];
__device__ __nv_bfloat16 g_attn_lo[T_MAX * NQ * HD];
__device__ __nv_bfloat16 g_wout_hi[NQ * HD * HID];
__device__ __nv_bfloat16 g_wout_lo[NQ * HD * HID];

__device__ __nv_bfloat16 g_q_hi[T_MAX * NQ * HD];
__device__ __nv_bfloat16 g_q_lo[T_MAX * NQ * HD];
__device__ __nv_bfloat16 g_k_hi[T_MAX * NKV * HD];
__device__ __nv_bfloat16 g_k_lo[T_MAX * NKV * HD];
__device__ __nv_bfloat16 g_v_hi[T_MAX * NKV * HD];
__device__ __nv_bfloat16 g_v_lo[T_MAX * NKV * HD];

// ---------------------------------------------------------------------------
// PTX helpers
// ---------------------------------------------------------------------------
__device__ __forceinline__ void cp16(uint32_t dst, const void* src) {
    asm volatile("cp.async.cg.shared.global [%0], [%1], 16;" :: "r"(dst), "l"(src));
}
__device__ __forceinline__ void cp_commit() {
    asm volatile("cp.async.commit_group;");
}
__device__ __forceinline__ void cp_wait1() {
    asm volatile("cp.async.wait_group 1;");
}
__device__ __forceinline__ void cp_wait2() {
    asm volatile("cp.async.wait_group 2;");
}
__device__ __forceinline__ void ldm_x4(uint32_t* r, uint32_t a) {
    asm volatile("ldmatrix.sync.aligned.m8n8.x4.shared.b16 {%0,%1,%2,%3}, [%4];"
        : "=r"(r[0]), "=r"(r[1]), "=r"(r[2]), "=r"(r[3]) : "r"(a));
}
__device__ __forceinline__ void ldm_x4_t(uint32_t* r, uint32_t a) {
    asm volatile("ldmatrix.sync.aligned.m8n8.x4.trans.shared.b16 {%0,%1,%2,%3}, [%4];"
        : "=r"(r[0]), "=r"(r[1]), "=r"(r[2]), "=r"(r[3]) : "r"(a));
}
__device__ __forceinline__ void mma16816(float* c, const uint32_t* a, const uint32_t* b) {
    asm volatile(
        "mma.sync.aligned.m16n8k16.row.col.f32.bf16.bf16.f32 "
        "{%0,%1,%2,%3}, {%4,%5,%6,%7}, {%8,%9}, {%0,%1,%2,%3};"
        : "+f"(c[0]), "+f"(c[1]), "+f"(c[2]), "+f"(c[3])
        : "r"(a[0]), "r"(a[1]), "r"(a[2]), "r"(a[3]), "r"(b[0]), "r"(b[1]));
}
__device__ __forceinline__ uint32_t smem_u32(const void* p) {
    return (uint32_t)__cvta_generic_to_shared(p);
}
__device__ __forceinline__ uint32_t pack_bf2(__nv_bfloat16 lo, __nv_bfloat16 hi) {
    __nv_bfloat162 v = __halves2bfloat162(lo, hi);
    return *(uint32_t*)&v;
}

// ---------------------------------------------------------------------------
// Split fp32 -> (hi, lo) bf16 pair
// ---------------------------------------------------------------------------
__global__ __launch_bounds__(256) void split_kernel(
    const float* __restrict__ x, __nv_bfloat16* __restrict__ hi,
    __nv_bfloat16* __restrict__ lo, int n)
{
    int i = (blockIdx.x * 256 + threadIdx.x) * 4;
    if (i >= n) { return; }
    float4 v = *(const float4*)(x + i);
    __nv_bfloat16 h0 = __float2bfloat16_rn(v.x);
    __nv_bfloat16 h1 = __float2bfloat16_rn(v.y);
    __nv_bfloat16 h2 = __float2bfloat16_rn(v.z);
    __nv_bfloat16 h3 = __float2bfloat16_rn(v.w);
    __nv_bfloat16 l0 = __float2bfloat16_rn(v.x - __bfloat162float(h0));
    __nv_bfloat16 l1 = __float2bfloat16_rn(v.y - __bfloat162float(h1));
    __nv_bfloat16 l2 = __float2bfloat16_rn(v.z - __bfloat162float(h2));
    __nv_bfloat16 l3 = __float2bfloat16_rn(v.w - __bfloat162float(h3));
    *(__nv_bfloat162*)(hi + i)     = __halves2bfloat162(h0, h1);
    *(__nv_bfloat162*)(hi + i + 2) = __halves2bfloat162(h2, h3);
    *(__nv_bfloat162*)(lo + i)     = __halves2bfloat162(l0, l1);
    *(__nv_bfloat162*)(lo + i + 2) = __halves2bfloat162(l2, l3);
}

// ---------------------------------------------------------------------------
// bf16x3 GEMM (R10/R12 config): tile 128x128, GBK=16, 4-stage ring,
// 128 threads (4 warps, 2m x 2n, warp tile 64x64), 2 CTAs/SM.
// Split-K via gridDim.z (uneven allowed). Epilogue atomicAdd when split.
// ---------------------------------------------------------------------------
#define GBM 128
#define GBN 128
#define GBK 16
#define SA  24                       // A row stride: 48B (R5-verified)
#define SB  136                      // B row stride: 272B (R5-verified)
#define A_STAGE (2 * GBM * SA)       // 6144 elems
#define B_STAGE (2 * GBK * SB)       // 4352 elems
#define G_SMEM_BYTES ((4 * A_STAGE + 4 * B_STAGE) * 2)   // 83968

__device__ __forceinline__ void g_fill_stage(
    uint32_t as_base, uint32_t bs_base,
    const __nv_bfloat16* __restrict__ Ahi, const __nv_bfloat16* __restrict__ Alo,
    const __nv_bfloat16* __restrict__ Bhi, const __nv_bfloat16* __restrict__ Blo,
    int bm, int bn, int k0, int K, int N, int tid)
{
    #pragma unroll
    for (int i = 0; i < 2; i++) {
        int idx = i * 128 + tid;
        int a_row = idx >> 1;
        int a_c   = (idx & 1) * 8;
        size_t aoff = (size_t)(bm + a_row) * K + k0 + a_c;
        uint32_t so = (uint32_t)((a_row * SA + a_c) * 2);
        cp16(as_base + so, Ahi + aoff);
        cp16(as_base + GBM * SA * 2 + so, Alo + aoff);

        int b_row = idx >> 4;
        int b_col = (idx & 15) * 8;
        size_t boff = (size_t)(k0 + b_row) * N + bn + b_col;
        uint32_t sbo = (uint32_t)((b_row * SB + b_col) * 2);
        cp16(bs_base + sbo, Bhi + boff);
        cp16(bs_base + GBK * SB * 2 + sbo, Blo + boff);
    }
}

__global__ __launch_bounds__(128, 2) void gemm_bf16x3(
    const __nv_bfloat16* __restrict__ Ahi, const __nv_bfloat16* __restrict__ Alo,
    const __nv_bfloat16* __restrict__ Bhi, const __nv_bfloat16* __restrict__ Blo,
    float* __restrict__ C, int M, int N, int K)
{
    extern __shared__ __nv_bfloat16 sm[];
    __nv_bfloat16* As = sm;                 // [4 stages][hi|lo][128*SA]
    __nv_bfloat16* Bs = sm + 4 * A_STAGE;   // [4 stages][hi|lo][16*SB]

    const int tid  = threadIdx.x;
    const int lane = tid & 31;
    const int warp = tid >> 5;
    const int wm   = warp >> 1;    // 0..1
    const int wn   = warp & 1;     // 0..1
    const int bm   = blockIdx.y * GBM;
    const int bn   = blockIdx.x * GBN;

    // uneven split-K: totIters split as base + (z < rem)
    const int totIters = K / GBK;
    const int zc  = gridDim.z;
    const int z   = blockIdx.z;
    const int bIt = totIters / zc;
    const int rem = totIters % zc;
    const int niter = bIt + ((z < rem) ? 1 : 0);
    const int kBase = (z * bIt + ((z < rem) ? z : rem)) * GBK;

    float acc[4][8][4];
    #pragma unroll
    for (int mi = 0; mi < 4; mi++) {
        #pragma unroll
        for (int ni = 0; ni < 8; ni++) {
            acc[mi][ni][0] = 0.0f;
            acc[mi][ni][1] = 0.0f;
            acc[mi][ni][2] = 0.0f;
            acc[mi][ni][3] = 0.0f;
        }
    }

    const uint32_t as0 = smem_u32(As);
    const uint32_t bs0 = smem_u32(Bs);

    // prologue: stages 0,1,2
    #pragma unroll
    for (int p = 0; p < 3; p++) {
        if (p < niter) {
            g_fill_stage(as0 + p * A_STAGE * 2, bs0 + p * B_STAGE * 2,
                         Ahi, Alo, Bhi, Blo, bm, bn, kBase + p * GBK, K, N, tid);
        }
        cp_commit();
    }

    for (int it = 0; it < niter; ++it) {
        cp_wait2();
        __syncthreads();

        if (it + 3 < niter) {
            int s = (it + 3) & 3;
            g_fill_stage(as0 + s * A_STAGE * 2, bs0 + s * B_STAGE * 2,
                         Ahi, Alo, Bhi, Blo, bm, bn, kBase + (it + 3) * GBK, K, N, tid);
        }
        cp_commit();

        const int s = it & 3;
        __nv_bfloat16* asb = As + s * A_STAGE;
        __nv_bfloat16* bsb = Bs + s * B_STAGE;

        uint32_t ah[4][4];
        uint32_t al[4][4];

        #pragma unroll
        for (int mi = 0; mi < 4; mi++) {
            int r = wm * 64 + mi * 16 + (lane & 15);
            int c = (lane >> 4) * 8;
            ldm_x4(ah[mi], smem_u32(asb + r * SA + c));
            ldm_x4(al[mi], smem_u32(asb + GBM * SA + r * SA + c));
        }

        #pragma unroll
        for (int bi = 0; bi < 4; bi++) {
            int r = lane & 15;
            int c = wn * 64 + bi * 16 + (lane >> 4) * 8;
            uint32_t t0[4];
            uint32_t t1[4];
            ldm_x4_t(t0, smem_u32(bsb + r * SB + c));
            ldm_x4_t(t1, smem_u32(bsb + GBK * SB + r * SB + c));
            uint32_t bh0[2]; bh0[0] = t0[0]; bh0[1] = t0[1];
            uint32_t bh1[2]; bh1[0] = t0[2]; bh1[1] = t0[3];
            uint32_t bl0[2]; bl0[0] = t1[0]; bl0[1] = t1[1];
            uint32_t bl1[2]; bl1[0] = t1[2]; bl1[1] = t1[3];

            #pragma unroll
            for (int mi = 0; mi < 4; mi++) {
                mma16816(acc[mi][2 * bi],     ah[mi], bh0);
                mma16816(acc[mi][2 * bi + 1], ah[mi], bh1);
            }
            #pragma unroll
            for (int mi = 0; mi < 4; mi++) {
                mma16816(acc[mi][2 * bi],     ah[mi], bl0);
                mma16816(acc[mi][2 * bi + 1], ah[mi], bl1);
            }
            #pragma unroll
            for (int mi = 0; mi < 4; mi++) {
                mma16816(acc[mi][2 * bi],     al[mi], bh0);
                mma16816(acc[mi][2 * bi + 1], al[mi], bh1);
            }
        }
    }

    const bool split = (gridDim.z > 1);
    #pragma unroll
    for (int mi = 0; mi < 4; mi++) {
        #pragma unroll
        for (int ni = 0; ni < 8; ni++) {
            int r = bm + wm * 64 + mi * 16 + (lane >> 2);
            int c = bn + wn * 64 + ni * 8 + (lane & 3) * 2;
            float* p0 = &C[(size_t)r * N + c];
            float* p1 = &C[(size_t)(r + 8) * N + c];
            if (split) {
                atomicAdd(p0,     acc[mi][ni][0]);
                atomicAdd(p0 + 1, acc[mi][ni][1]);
                atomicAdd(p1,     acc[mi][ni][2]);
                atomicAdd(p1 + 1, acc[mi][ni][3]);
            } else {
                float2 v0;
                float2 v1;
                v0.x = acc[mi][ni][0];
                v0.y = acc[mi][ni][1];
                v1.x = acc[mi][ni][2];
                v1.y = acc[mi][ni][3];
                *(float2*)p0 = v0;
                *(float2*)p1 = v1;
            }
        }
    }
}

// ---------------------------------------------------------------------------
// RMSNorm + RoPE + split, one warp per (token, head). Lane owns (d, d+32).
// ---------------------------------------------------------------------------
__global__ __launch_bounds__(256) void norm_rope_split_kernel(
    const float* __restrict__ qkv, const int* __restrict__ positions,
    const float* __restrict__ q_ln_w, const float* __restrict__ k_ln_w,
    __nv_bfloat16* __restrict__ qhi, __nv_bfloat16* __restrict__ qlo,
    __nv_bfloat16* __restrict__ khi, __nv_bfloat16* __restrict__ klo,
    __nv_bfloat16* __restrict__ vhi, __nv_bfloat16* __restrict__ vlo)
{
    const int gw   = blockIdx.x * 8 + (threadIdx.x >> 5);
    const int lane = threadIdx.x & 31;
    const int head = gw % (NQ + 2 * NKV);
    const int t    = gw / (NQ + 2 * NKV);

    if (head >= NQ + NKV) {
        int vh = head - NQ - NKV;
        const float* base = qkv + (size_t)t * QKV_COLS + V_OFF + vh * HD;
        float x1 = base[lane];
        float x2 = base[lane + 32];
        __nv_bfloat16 h1 = __float2bfloat16_rn(x1);
        __nv_bfloat16 h2 = __float2bfloat16_rn(x2);
        size_t o = (size_t)t * (NKV * HD) + vh * HD + lane;
        vhi[o]      = h1;
        vhi[o + 32] = h2;
        vlo[o]      = __float2bfloat16_rn(x1 - __bfloat162float(h1));
        vlo[o + 32] = __float2bfloat16_rn(x2 - __bfloat162float(h2));
        return;
    }

    const bool isq = (head < NQ);
    const float* base = qkv + (size_t)t * QKV_COLS +
                        (isq ? head * HD : K_OFF + (head - NQ) * HD);
    const float* w = isq ? q_ln_w : k_ln_w;

    float x1 = base[lane];
    float x2 = base[lane + 32];
    float ss = x1 * x1 + x2 * x2;
    #pragma unroll
    for (int o = 16; o > 0; o >>= 1) {
        ss += __shfl_xor_sync(0xffffffff, ss, o);
    }
    float rs = rsqrtf(ss * (1.0f / 64.0f) + 1e-5f);
    float y1 = x1 * rs * w[lane];
    float y2 = x2 * rs * w[lane + 32];

    float pos = (float)positions[t];
    // inv = 1e6^(-lane/32) = exp2f(-lane * log2(1e6)/32), log2(1e6)/32 = 0.62286152
    float inv = exp2f((float)lane * (-0.62286152f));
    float s, c;
    sincosf(pos * inv, &s, &c);
    float o1 = y1 * c - y2 * s;
    float o2 = y2 * c + y1 * s;
    if (isq) {
        o1 *= 0.125f;
        o2 *= 0.125f;
    }

    __nv_bfloat16 h1 = __float2bfloat16_rn(o1);
    __nv_bfloat16 h2 = __float2bfloat16_rn(o2);
    __nv_bfloat16 l1 = __float2bfloat16_rn(o1 - __bfloat162float(h1));
    __nv_bfloat16 l2 = __float2bfloat16_rn(o2 - __bfloat162float(h2));
    if (isq) {
        size_t o = (size_t)t * (NQ * HD) + head * HD + lane;
        qhi[o]      = h1;
        qhi[o + 32] = h2;
        qlo[o]      = l1;
        qlo[o + 32] = l2;
    } else {
        size_t o = (size_t)t * (NKV * HD) + (head - NQ) * HD + lane;
        khi[o]      = h1;
        khi[o + 32] = h2;
        klo[o]      = l1;
        klo[o + 32] = l2;
    }
}

// ---------------------------------------------------------------------------
// Tensor-core causal flash attention (bf16x3, mma.sync).
// PAIRED q-tiles: block (pq, h) handles q-tiles (NT-1-pq) then (pq).
// Every block does exactly NT+2 tile-iters -> one uniform wave (256 blocks).
// ---------------------------------------------------------------------------
#define AST 72
#define AREG (4 * 64 * AST)
#define A_SMEM_BYTES (3 * AREG * 2)

__global__ __launch_bounds__(256, 2) void attn_mma_kernel(
    const __nv_bfloat16* __restrict__ qhi, const __nv_bfloat16* __restrict__ qlo,
    const __nv_bfloat16* __restrict__ khi, const __nv_bfloat16* __restrict__ klo,
    const __nv_bfloat16* __restrict__ vhi, const __nv_bfloat16* __restrict__ vlo,
    __nv_bfloat16* __restrict__ ohi, __nv_bfloat16* __restrict__ olo)
{
    extern __shared__ __nv_bfloat16 sm[];

    const int tid  = threadIdx.x;
    const int lane = tid & 31;
    const int warp = tid >> 5;
    const int h    = blockIdx.y;
    const int kvh  = h >> 2;

    for (int pass = 0; pass < 2; pass++) {
        const int qtile = (pass == 0) ? (2 * gridDim.x - 1 - blockIdx.x)
                                      : blockIdx.x;
        const int qbase = qtile * 128;
        const int ntiles = 2 * qtile + 2;

        // ---- prologue: Q into region0 + KV tile0 into region1 (group0) ----
        #pragma unroll
        for (int i = 0; i < 4; i++) {
            int lin = i * 256 + tid;
            int row = lin >> 3;
            int c = (lin & 7) * 8;
            size_t g = (size_t)(qbase + row) * (NQ * HD) + h * HD + c;
            cp16(smem_u32(sm + row * AST + c), qhi + g);
            cp16(smem_u32(sm + 128 * AST + row * AST + c), qlo + g);
        }
        {
            __nv_bfloat16* rb = sm + AREG;
            #pragma unroll
            for (int i = 0; i < 2; i++) {
                int lin = i * 256 + tid;
                int row = lin >> 3;
                int c = (lin & 7) * 8;
                size_t g = (size_t)row * (NKV * HD) + kvh * HD + c;
                cp16(smem_u32(rb + row * AST + c), khi + g);
                cp16(smem_u32(rb + 64 * AST + row * AST + c), klo + g);
                cp16(smem_u32(rb + 128 * AST + row * AST + c), vhi + g);
                cp16(smem_u32(rb + 192 * AST + row * AST + c), vlo + g);
            }
        }
        cp_commit();
        if (ntiles > 1) {
            __nv_bfloat16* rb = sm + 2 * AREG;
            #pragma unroll
            for (int i = 0; i < 2; i++) {
                int lin = i * 256 + tid;
                int row = lin >> 3;
                int c = (lin & 7) * 8;
                size_t g = (size_t)(64 + row) * (NKV * HD) + kvh * HD + c;
                cp16(smem_u32(rb + row * AST + c), khi + g);
                cp16(smem_u32(rb + 64 * AST + row * AST + c), klo + g);
                cp16(smem_u32(rb + 128 * AST + row * AST + c), vhi + g);
                cp16(smem_u32(rb + 192 * AST + row * AST + c), vlo + g);
            }
        }
        cp_commit();

        cp_wait1();
        __syncthreads();

        uint32_t aqh[4][4];
        uint32_t aql[4][4];
        #pragma unroll
        for (int ks = 0; ks < 4; ks++) {
            int r = warp * 16 + (lane & 15);
            int c = ks * 16 + (lane >> 4) * 8;
            ldm_x4(aqh[ks], smem_u32(sm + r * AST + c));
            ldm_x4(aql[ks], smem_u32(sm + 128 * AST + r * AST + c));
        }
        __syncthreads();

        float oacc[8][4];
        #pragma unroll
        for (int ni = 0; ni < 8; ni++) {
            oacc[ni][0] = 0.0f; oacc[ni][1] = 0.0f;
            oacc[ni][2] = 0.0f; oacc[ni][3] = 0.0f;
        }
        float m0 = -1e30f, m1 = -1e30f, l0 = 0.0f, l1 = 0.0f;

        const int rowlim = qbase + warp * 16 + 15;

        for (int it = 0; it < ntiles; it++) {
            cp_wait1();
            __syncthreads();

            if (it + 2 < ntiles) {
                __nv_bfloat16* rb = sm + ((it + 3) % 3) * AREG;
                int k0n = (it + 2) * 64;
                #pragma unroll
                for (int i = 0; i < 2; i++) {
                    int lin = i * 256 + tid;
                    int row = lin >> 3;
                    int c = (lin & 7) * 8;
                    size_t g = (size_t)(k0n + row) * (NKV * HD) + kvh * HD + c;
                    cp16(smem_u32(rb + row * AST + c), khi + g);
                    cp16(smem_u32(rb + 64 * AST + row * AST + c), klo + g);
                    cp16(smem_u32(rb + 128 * AST + row * AST + c), vhi + g);
                    cp16(smem_u32(rb + 192 * AST + row * AST + c), vlo + g);
                }
            }
            cp_commit();

            const int k0 = it * 64;
            if (k0 > rowlim) { continue; }

            __nv_bfloat16* rb = sm + ((it + 1) % 3) * AREG;
            __nv_bfloat16* kbh = rb;
            __nv_bfloat16* kbl = rb + 64 * AST;
            __nv_bfloat16* vbh = rb + 128 * AST;
            __nv_bfloat16* vbl = rb + 192 * AST;

            float sacc[8][4];
            #pragma unroll
            for (int ni = 0; ni < 8; ni++) {
                sacc[ni][0] = 0.0f; sacc[ni][1] = 0.0f;
                sacc[ni][2] = 0.0f; sacc[ni][3] = 0.0f;
            }

            const int krow = ((lane >> 4) << 3) + (lane & 7);
            #pragma unroll
            for (int ks = 0; ks < 4; ks++) {
                int kcol = ks * 16 + ((lane >> 3) & 1) * 8;
                #pragma unroll
                for (int kg = 0; kg < 4; kg++) {
                    uint32_t th[4];
                    uint32_t tl[4];
                    ldm_x4(th, smem_u32(kbh + (kg * 16 + krow) * AST + kcol));
                    ldm_x4(tl, smem_u32(kbl + (kg * 16 + krow) * AST + kcol));
                    uint32_t b0h[2]; b0h[0] = th[0]; b0h[1] = th[1];
                    uint32_t b1h[2]; b1h[0] = th[2]; b1h[1] = th[3];
                    uint32_t b0l[2]; b0l[0] = tl[0]; b0l[1] = tl[1];
                    uint32_t b1l[2]; b1l[0] = tl[2]; b1l[1] = tl[3];
                    mma16816(sacc[2 * kg],     aqh[ks], b0h);
                    mma16816(sacc[2 * kg + 1], aqh[ks], b1h);
                    mma16816(sacc[2 * kg],     aqh[ks], b0l);
                    mma16816(sacc[2 * kg + 1], aqh[ks], b1l);
                    mma16816(sacc[2 * kg],     aql[ks], b0h);
                    mma16816(sacc[2 * kg + 1], aql[ks], b1h);
                }
            }

            if (k0 + 64 > qbase + warp * 16) {
                int row0 = qbase + warp * 16 + (lane >> 2);
                #pragma unroll
                for (int ni = 0; ni < 8; ni++) {
                    int colk = k0 + ni * 8 + (lane & 3) * 2;
                    if (colk     > row0)     { sacc[ni][0] = -1e30f; }
                    if (colk + 1 > row0)     { sacc[ni][1] = -1e30f; }
                    if (colk     > row0 + 8) { sacc[ni][2] = -1e30f; }
                    if (colk + 1 > row0 + 8) { sacc[ni][3] = -1e30f; }
                }
            }

            float nm0 = m0;
            float nm1 = m1;
            #pragma unroll
            for (int ni = 0; ni < 8; ni++) {
                nm0 = fmaxf(nm0, fmaxf(sacc[ni][0], sacc[ni][1]));
                nm1 = fmaxf(nm1, fmaxf(sacc[ni][2], sacc[ni][3]));
            }
            nm0 = fmaxf(nm0, __shfl_xor_sync(0xffffffff, nm0, 1));
            nm0 = fmaxf(nm0, __shfl_xor_sync(0xffffffff, nm0, 2));
            nm1 = fmaxf(nm1, __shfl_xor_sync(0xffffffff, nm1, 1));
            nm1 = fmaxf(nm1, __shfl_xor_sync(0xffffffff, nm1, 2));

            float sc0 = __expf(m0 - nm0);
            float sc1 = __expf(m1 - nm1);
            m0 = nm0;
            m1 = nm1;
            l0 *= sc0;
            l1 *= sc1;

            uint32_t phi[8][2];
            uint32_t plo[8][2];
            #pragma unroll
            for (int ni = 0; ni < 8; ni++) {
                float p0 = __expf(sacc[ni][0] - nm0);
                float p1 = __expf(sacc[ni][1] - nm0);
                float p2 = __expf(sacc[ni][2] - nm1);
                float p3 = __expf(sacc[ni][3] - nm1);
                l0 += p0 + p1;
                l1 += p2 + p3;
                __nv_bfloat16 h0 = __float2bfloat16_rn(p0);
                __nv_bfloat16 h1 = __float2bfloat16_rn(p1);
                __nv_bfloat16 h2 = __float2bfloat16_rn(p2);
                __nv_bfloat16 h3 = __float2bfloat16_rn(p3);
                phi[ni][0] = pack_bf2(h0, h1);
                phi[ni][1] = pack_bf2(h2, h3);
                plo[ni][0] = pack_bf2(__float2bfloat16_rn(p0 - __bfloat162float(h0)),
                                      __float2bfloat16_rn(p1 - __bfloat162float(h1)));
                plo[ni][1] = pack_bf2(__float2bfloat16_rn(p2 - __bfloat162float(h2)),
                                      __float2bfloat16_rn(p3 - __bfloat162float(h3)));
                oacc[ni][0] *= sc0;
                oacc[ni][1] *= sc0;
                oacc[ni][2] *= sc1;
                oacc[ni][3] *= sc1;
            }

            #pragma unroll
            for (int ks = 0; ks < 4; ks++) {
                uint32_t aph[4];
                uint32_t apl[4];
                aph[0] = phi[2 * ks][0];     aph[1] = phi[2 * ks][1];
                aph[2] = phi[2 * ks + 1][0]; aph[3] = phi[2 * ks + 1][1];
                apl[0] = plo[2 * ks][0];     apl[1] = plo[2 * ks][1];
                apl[2] = plo[2 * ks + 1][0]; apl[3] = plo[2 * ks + 1][1];
                int vrow = ks * 16 + (lane & 15);
                #pragma unroll
                for (int nd = 0; nd < 4; nd++) {
                    int vcol = nd * 16 + (lane >> 4) * 8;
                    uint32_t th[4];
                    uint32_t tl[4];
                    ldm_x4_t(th, smem_u32(vbh + vrow * AST + vcol));
                    ldm_x4_t(tl, smem_u32(vbl + vrow * AST + vcol));
                    uint32_t b0h[2]; b0h[0] = th[0]; b0h[1] = th[1];
                    uint32_t b1h[2]; b1h[0] = th[2]; b1h[1] = th[3];
                    uint32_t b0l[2]; b0l[0] = tl[0]; b0l[1] = tl[1];
                    uint32_t b1l[2]; b1l[0] = tl[2]; b1l[1] = tl[3];
                    mma16816(oacc[2 * nd],     aph, b0h);
                    mma16816(oacc[2 * nd + 1], aph, b1h);
                    mma16816(oacc[2 * nd],     aph, b0l);
                    mma16816(oacc[2 * nd + 1], aph, b1l);
                    mma16816(oacc[2 * nd],     apl, b0h);
                    mma16816(oacc[2 * nd + 1], apl, b1h);
                }
            }
        }

        l0 += __shfl_xor_sync(0xffffffff, l0, 1);
        l0 += __shfl_xor_sync(0xffffffff, l0, 2);
        l1 += __shfl_xor_sync(0xffffffff, l1, 1);
        l1 += __shfl_xor_sync(0xffffffff, l1, 2);
        float inv0 = 1.0f / l0;
        float inv1 = 1.0f / l1;

        int row0 = qbase + warp * 16 + (lane >> 2);
        #pragma unroll
        for (int ni = 0; ni < 8; ni++) {
            int col = h * HD + ni * 8 + (lane & 3) * 2;
            float f0 = oacc[ni][0] * inv0;
            float f1 = oacc[ni][1] * inv0;
            float f2 = oacc[ni][2] * inv1;
            float f3 = oacc[ni][3] * inv1;
            __nv_bfloat16 h0 = __float2bfloat16_rn(f0);
            __nv_bfloat16 h1 = __float2bfloat16_rn(f1);
            __nv_bfloat16 h2 = __float2bfloat16_rn(f2);
            __nv_bfloat16 h3 = __float2bfloat16_rn(f3);
            __nv_bfloat162 hv0 = __halves2bfloat162(h0, h1);
            __nv_bfloat162 hv1 = __halves2bfloat162(h2, h3);
            __nv_bfloat162 lv0 = __halves2bfloat162(
                __float2bfloat16_rn(f0 - __bfloat162float(h0)),
                __float2bfloat16_rn(f1 - __bfloat162float(h1)));
            __nv_bfloat162 lv1 = __halves2bfloat162(
                __float2bfloat16_rn(f2 - __bfloat162float(h2)),
                __float2bfloat16_rn(f3 - __bfloat162float(h3)));
            *(__nv_bfloat162*)&ohi[(size_t)row0 * (NQ * HD) + col] = hv0;
            *(__nv_bfloat162*)&olo[(size_t)row0 * (NQ * HD) + col] = lv0;
            *(__nv_bfloat162*)&ohi[(size_t)(row0 + 8) * (NQ * HD) + col] = hv1;
            *(__nv_bfloat162*)&olo[(size_t)(row0 + 8) * (NQ * HD) + col] = lv1;
        }

        __syncthreads();   // drain before next pass reuses smem regions
    }
}

// ---------------------------------------------------------------------------
// Launch
// ---------------------------------------------------------------------------
extern "C" void kernel_launch(void* const* d_in, const int* in_sizes, int n_in,
                              void* d_out, int out_size)
{
    const int*   positions = (const int*)d_in[0];
    const float* hidden    = (const float*)d_in[1];
    const float* w_qkv     = (const float*)d_in[2];
    const float* w_out     = (const float*)d_in[3];
    const float* q_ln_w    = (const float*)d_in[4];
    const float* k_ln_w    = (const float*)d_in[5];
    float* out = (float*)d_out;

    const int T = in_sizes[1] / HID;   // 2048

    float* qkv;
    __nv_bfloat16 *hid_hi, *hid_lo, *wqkv_hi, *wqkv_lo;
    __nv_bfloat16 *attn_hi, *attn_lo, *wout_hi, *wout_lo;
    __nv_bfloat16 *q_hi, *q_lo, *k_hi, *k_lo, *v_hi, *v_lo;
    cudaGetSymbolAddress((void**)&qkv, g_qkv);
    cudaGetSymbolAddress((void**)&hid_hi, g_hid_hi);
    cudaGetSymbolAddress((void**)&hid_lo, g_hid_lo);
    cudaGetSymbolAddress((void**)&wqkv_hi, g_wqkv_hi);
    cudaGetSymbolAddress((void**)&wqkv_lo, g_wqkv_lo);
    cudaGetSymbolAddress((void**)&attn_hi, g_attn_hi);
    cudaGetSymbolAddress((void**)&attn_lo, g_attn_lo);
    cudaGetSymbolAddress((void**)&wout_hi, g_wout_hi);
    cudaGetSymbolAddress((void**)&wout_lo, g_wout_lo);
    cudaGetSymbolAddress((void**)&q_hi, g_q_hi);
    cudaGetSymbolAddress((void**)&q_lo, g_q_lo);
    cudaGetSymbolAddress((void**)&k_hi, g_k_hi);
    cudaGetSymbolAddress((void**)&k_lo, g_k_lo);
    cudaGetSymbolAddress((void**)&v_hi, g_v_hi);
    cudaGetSymbolAddress((void**)&v_lo, g_v_lo);

    // Splits for GEMM inputs + zero qkv for split-K accumulation
    {
        cudaMemsetAsync(qkv, 0, (size_t)T * QKV_COLS * sizeof(float), 0);
        int n1 = T * HID;
        split_kernel<<<n1 / 1024, 256>>>(hidden, hid_hi, hid_lo, n1);
        int n2 = HID * QKV_COLS;
        split_kernel<<<n2 / 1024, 256>>>(w_qkv, wqkv_hi, wqkv_lo, n2);
        int n3 = NQ * HD * HID;
        split_kernel<<<n3 / 1024, 256>>>(w_out, wout_hi, wout_lo, n3);
    }

    cudaFuncSetAttribute(gemm_bf16x3,
                         cudaFuncAttributeMaxDynamicSharedMemorySize, G_SMEM_BYTES);

    // 1) QKV projection (uneven split-K=3: work-stealing packs 1152 slices)
    {
        dim3 grid(QKV_COLS / GBN, T / GBM, 3);
        gemm_bf16x3<<<grid, 128, G_SMEM_BYTES>>>(hid_hi, hid_lo, wqkv_hi, wqkv_lo,
                                                 qkv, T, QKV_COLS, HID);
    }

    // 2) RMSNorm + RoPE + split (q scaled by 1/8)
    {
        int nwarps = T * (NQ + 2 * NKV);
        norm_rope_split_kernel<<<nwarps / 8, 256>>>(qkv, positions, q_ln_w, k_ln_w,
                                                    q_hi, q_lo, k_hi, k_lo, v_hi, v_lo);
    }

    // 3) Paired-tile causal attention: 8 pairs x 32 heads = 256 uniform blocks
    {
        cudaFuncSetAttribute(attn_mma_kernel,
                             cudaFuncAttributeMaxDynamicSharedMemorySize, A_SMEM_BYTES);
        dim3 grid(T / 128 / 2, NQ);
        attn_mma_kernel<<<grid, 256, A_SMEM_BYTES>>>(q_hi, q_lo, k_hi, k_lo,
                                                     v_hi, v_lo, attn_hi, attn_lo);
    }

    // 4) Output projection (single wave, no split: atomics cost > packing gain)
    {
        dim3 grid(HID / GBN, T / GBM, 1);
        gemm_bf16x3<<<grid, 128, G_SMEM_BYTES>>>(attn_hi, attn_lo, wout_hi, wout_lo,
                                                 out, T, HID, NQ * HD);
    }
}